// round 8
// baseline (speedup 1.0000x reference)
#include <cuda_runtime.h>

// x: (N=8, M=32, C=128, H=32, W=32) fp32.  D = H*W = 1024.
// 4096 independent classical Gram-Schmidt problems (one per (m,c)),
// each over NV=8 vectors of length 1024.
//
// One block of 512 threads per problem, 1 float2 per thread per vector
// (structural register reduction: ~40 regs -> 3 CTAs/SM, 48 warps, without
// compiler-forced spills).
//  A) load 8 float2, 36 packed-Gram dot2s, 1 shuffle pre-reduce,
//     STS to part[t][warp*16+lane'] (36KB)
//  B) 16 warps cooperatively reduce the 36 entries
//  C) warp 0: triangular recursion Gram -> T (GS transform, inv norms on
//     the diagonal), broadcast via smem
//  D) apply b_i = sum_{k<=i} T[i][k] v_k, store.
#define NV 8
#define DLEN 1024
#define NPROB 4096
#define NSTRIDE_F2 (NPROB * DLEN / 2)   // 2097152 float2 between n-slices
#define NG 36                           // lower-triangular entries
#define NT 512

__device__ __forceinline__ float dot2(float2 a, float2 b) {
    return a.x * b.x + a.y * b.y;
}

__global__ void __launch_bounds__(NT, 3)
gram_schmidt_kernel(const float* __restrict__ x, float* __restrict__ out) {
    const int p    = blockIdx.x;
    const int tid  = threadIdx.x;
    const int lane = tid & 31;
    const int warp = tid >> 5;      // 0..15

    const float2* __restrict__ xin =
        reinterpret_cast<const float2*>(x) + (size_t)p * (DLEN / 2) + tid;
    float2* __restrict__ xout =
        reinterpret_cast<float2*>(out) + (size_t)p * (DLEN / 2) + tid;

    __shared__ float part[NG][256];  // 36KB: half-reduced Gram partials
    __shared__ float Gf[NG];         // reduced Gram (packed lower tri)
    __shared__ float Tm[NG];         // GS transform matrix (packed lower tri)

    // ---- A: load all 8 vector slices (batched LDG.64, coalesced) ----
    float2 v[NV];
    #pragma unroll
    for (int n = 0; n < NV; n++) v[n] = xin[(size_t)n * NSTRIDE_F2];

    // partial Gram, pre-reduced one shuffle round (lanes 0-15 store)
    #pragma unroll
    for (int i = 0; i < NV; i++) {
        #pragma unroll
        for (int j = 0; j <= i; j++) {
            float s = dot2(v[i], v[j]);
            s += __shfl_xor_sync(0xffffffffu, s, 16);
            if (lane < 16) part[i * (i + 1) / 2 + j][warp * 16 + lane] = s;
        }
    }
    __syncthreads();

    // ---- B: cooperative reduction; warp w handles entries w, w+16, w+32 ----
    for (int t = warp; t < NG; t += 16) {
        const float4* row = reinterpret_cast<const float4*>(part[t]);
        float4 a = row[lane];            // 32 lanes x float4 = 128 floats
        float4 b = row[lane + 32];       // next 128 floats
        float s = ((a.x + a.y) + (a.z + a.w)) + ((b.x + b.y) + (b.z + b.w));
        s += __shfl_xor_sync(0xffffffffu, s, 16);
        s += __shfl_xor_sync(0xffffffffu, s, 8);
        s += __shfl_xor_sync(0xffffffffu, s, 4);
        s += __shfl_xor_sync(0xffffffffu, s, 2);
        s += __shfl_xor_sync(0xffffffffu, s, 1);
        if (lane == 0) Gf[t] = s;
    }
    __syncthreads();

    // ---- C: warp 0 computes the triangular recursion (replicated lanes) ----
    if (warp == 0) {
        float G[NG];
        #pragma unroll
        for (int t = 0; t < NG; t++) G[t] = Gf[t];  // broadcast LDS

        float T[NG];
        {
            float inv = (G[0] > 0.0f) ? rsqrtf(G[0]) : 0.0f;
            T[0] = inv;
        }
        #pragma unroll
        for (int i = 1; i < NV; i++) {
            float c[NV];
            #pragma unroll
            for (int j = 0; j < i; j++) {
                float s = 0.0f;
                #pragma unroll
                for (int k = 0; k <= j; k++)
                    s += T[j * (j + 1) / 2 + k] * G[i * (i + 1) / 2 + k];
                c[j] = s;
            }
            float n2 = G[i * (i + 1) / 2 + i];
            #pragma unroll
            for (int j = 0; j < i; j++) n2 -= c[j] * c[j];
            float inv = (n2 > 0.0f) ? rsqrtf(n2) : 0.0f;

            #pragma unroll
            for (int k = 0; k < i; k++) {
                float s = 0.0f;
                #pragma unroll
                for (int j = k; j < i; j++)
                    s -= c[j] * T[j * (j + 1) / 2 + k];
                T[i * (i + 1) / 2 + k] = s * inv;
            }
            T[i * (i + 1) / 2 + i] = inv;
        }
        if (lane == 0) {
            #pragma unroll
            for (int t = 0; t < NG; t++) Tm[t] = T[t];
        }
    }
    __syncthreads();

    // ---- D: apply b_i = sum_{k<=i} T[i][k] v_k, store ----
    #pragma unroll
    for (int i = 0; i < NV; i++) {
        float2 acc = make_float2(0.0f, 0.0f);
        #pragma unroll
        for (int k = 0; k <= i; k++) {
            float t = Tm[i * (i + 1) / 2 + k];  // LDS broadcast
            acc.x += t * v[k].x;
            acc.y += t * v[k].y;
        }
        xout[(size_t)i * NSTRIDE_F2] = acc;
    }
}

extern "C" void kernel_launch(void* const* d_in, const int* in_sizes, int n_in,
                              void* d_out, int out_size) {
    const float* x = (const float*)d_in[0];
    float* out = (float*)d_out;
    gram_schmidt_kernel<<<NPROB, NT>>>(x, out);
}

// round 10
// speedup vs baseline: 1.3696x; 1.3696x over previous
#include <cuda_runtime.h>
#include <cstdint>

// x: (N=8, M=32, C=128, H=32, W=32) fp32.  D = H*W = 1024.
// 4096 independent classical Gram-Schmidt problems (one per (m,c)),
// each over NV=8 vectors of length 1024.
//
// Two problems per block (grid=2048, 256 threads):
//  - p1 = bid is loaded with plain LDG.128 and processed exactly like the
//    best (R3) kernel.
//  - p2 = bid + 2048 is prefetched into a 32KB smem buffer via cp.async.cg
//    at block start, so its DRAM traffic streams in while p1 is in its
//    compute/barrier phases (the window where DRAM used to sit idle).
//  - after p1 is stored, wait for the prefetch and process p2 out of smem.
#define NV 8
#define DLEN 1024
#define NPROB 4096
#define NSTRIDE_F4 (NPROB * DLEN / 4)   // 1048576 float4 between n-slices
#define NG 36                           // lower-triangular entries
#define GRID 2048

__device__ __forceinline__ float dot4(float4 a, float4 b) {
    return a.x * b.x + a.y * b.y + a.z * b.z + a.w * b.w;
}

__device__ __forceinline__ void cp_async16(uint32_t smem_dst, const void* gsrc) {
    asm volatile("cp.async.cg.shared.global [%0], [%1], 16;\n"
                 :: "r"(smem_dst), "l"(gsrc));
}

struct SmemLayout {
    float4 buf[NV][256];   // 32KB prefetch buffer for p2
    float  part[NG][64];   // 9KB Gram partials (2-shuffle pre-reduced)
    float  Gf[NG];
    float  Tm[NG];
};

// Full R3-style pipeline on register-resident vectors v[], for problem
// row base pointers.  3 barriers.
__device__ __forceinline__ void process(float4 v[NV], float4* __restrict__ dst,
                                        SmemLayout* s, int tid, int lane, int warp) {
    // Gram partials, pre-reduced 2 shuffle rounds, lanes 0-7 store
    #pragma unroll
    for (int i = 0; i < NV; i++) {
        #pragma unroll
        for (int j = 0; j <= i; j++) {
            float t = dot4(v[i], v[j]);
            t += __shfl_xor_sync(0xffffffffu, t, 16);
            t += __shfl_xor_sync(0xffffffffu, t, 8);
            if (lane < 8) s->part[i * (i + 1) / 2 + j][warp * 8 + lane] = t;
        }
    }
    __syncthreads();

    // cooperative reduction: warp w handles entries w, w+8, ...
    for (int t = warp; t < NG; t += 8) {
        const float2* row = reinterpret_cast<const float2*>(s->part[t]);
        float2 a = row[lane];             // 32 lanes x float2 = 64 floats
        float r = a.x + a.y;
        r += __shfl_xor_sync(0xffffffffu, r, 16);
        r += __shfl_xor_sync(0xffffffffu, r, 8);
        r += __shfl_xor_sync(0xffffffffu, r, 4);
        r += __shfl_xor_sync(0xffffffffu, r, 2);
        r += __shfl_xor_sync(0xffffffffu, r, 1);
        if (lane == 0) s->Gf[t] = r;
    }
    __syncthreads();

    // warp 0: triangular recursion Gram -> T (inv norms on the diagonal)
    if (warp == 0) {
        float G[NG];
        #pragma unroll
        for (int t = 0; t < NG; t++) G[t] = s->Gf[t];

        float T[NG];
        {
            float inv = (G[0] > 0.0f) ? rsqrtf(G[0]) : 0.0f;
            T[0] = inv;
        }
        #pragma unroll
        for (int i = 1; i < NV; i++) {
            float c[NV];
            #pragma unroll
            for (int j = 0; j < i; j++) {
                float acc = 0.0f;
                #pragma unroll
                for (int k = 0; k <= j; k++)
                    acc += T[j * (j + 1) / 2 + k] * G[i * (i + 1) / 2 + k];
                c[j] = acc;
            }
            float n2 = G[i * (i + 1) / 2 + i];
            #pragma unroll
            for (int j = 0; j < i; j++) n2 -= c[j] * c[j];
            float inv = (n2 > 0.0f) ? rsqrtf(n2) : 0.0f;

            #pragma unroll
            for (int k = 0; k < i; k++) {
                float acc = 0.0f;
                #pragma unroll
                for (int j = k; j < i; j++)
                    acc -= c[j] * T[j * (j + 1) / 2 + k];
                T[i * (i + 1) / 2 + k] = acc * inv;
            }
            T[i * (i + 1) / 2 + i] = inv;
        }
        if (lane == 0) {
            #pragma unroll
            for (int t = 0; t < NG; t++) s->Tm[t] = T[t];
        }
    }
    __syncthreads();

    // apply b_i = sum_{k<=i} T[i][k] v_k, streaming store
    #pragma unroll
    for (int i = 0; i < NV; i++) {
        float4 acc = make_float4(0.0f, 0.0f, 0.0f, 0.0f);
        #pragma unroll
        for (int k = 0; k <= i; k++) {
            float t = s->Tm[i * (i + 1) / 2 + k];  // LDS broadcast
            acc.x += t * v[k].x;
            acc.y += t * v[k].y;
            acc.z += t * v[k].z;
            acc.w += t * v[k].w;
        }
        __stcs(&dst[(size_t)i * NSTRIDE_F4], acc);
    }
}

__global__ void __launch_bounds__(256, 4)
gram_schmidt_kernel(const float* __restrict__ x, float* __restrict__ out) {
    __shared__ SmemLayout s;

    const int tid  = threadIdx.x;
    const int lane = tid & 31;
    const int warp = tid >> 5;

    const int p1 = blockIdx.x;
    const int p2 = blockIdx.x + GRID;

    const float4* __restrict__ xin4 = reinterpret_cast<const float4*>(x);
    float4* __restrict__ out4 = reinterpret_cast<float4*>(out);

    // ---- kick off background prefetch of p2 into smem ----
    {
        const uint32_t b =
            (uint32_t)__cvta_generic_to_shared(&s.buf[0][0]) + (uint32_t)tid * 16u;
        const float4* src = xin4 + (size_t)p2 * (DLEN / 4) + tid;
        #pragma unroll
        for (int n = 0; n < NV; n++)
            cp_async16(b + (uint32_t)n * (256u * 16u), src + (size_t)n * NSTRIDE_F4);
        asm volatile("cp.async.commit_group;\n");
    }

    // ---- problem 1: plain LDG path (R3-proven) ----
    {
        const float4* src = xin4 + (size_t)p1 * (DLEN / 4) + tid;
        float4 v[NV];
        #pragma unroll
        for (int n = 0; n < NV; n++) v[n] = src[(size_t)n * NSTRIDE_F4];

        process(v, out4 + (size_t)p1 * (DLEN / 4) + tid, &s, tid, lane, warp);
    }

    // ---- problem 2: out of the prefetch buffer ----
    {
        asm volatile("cp.async.wait_group 0;\n" ::: "memory");
        __syncthreads();   // prefetch visible CTA-wide; also closes p1's use of part/Tm

        float4 v[NV];
        #pragma unroll
        for (int n = 0; n < NV; n++) v[n] = s.buf[n][tid];

        process(v, out4 + (size_t)p2 * (DLEN / 4) + tid, &s, tid, lane, warp);
    }
}

extern "C" void kernel_launch(void* const* d_in, const int* in_sizes, int n_in,
                              void* d_out, int out_size) {
    const float* x = (const float*)d_in[0];
    float* out = (float*)d_out;
    gram_schmidt_kernel<<<GRID, 256>>>(x, out);
}

// round 11
// speedup vs baseline: 1.4948x; 1.0914x over previous
#include <cuda_runtime.h>

// x: (N=8, M=32, C=128, H=32, W=32) fp32.  D = H*W = 1024.
// 4096 independent classical Gram-Schmidt problems (one per (m,c)),
// each over NV=8 vectors of length 1024.
//
// One block (256 threads) per problem, 1 float4/thread/vector (R3 shape —
// empirically the best overlap comes from the CTA scheduler pipelining many
// small blocks, not from manual cp.async pipelines).
//  A) __ldcg load 8 float4 (L1 bypass, single-touch data), 36 packed-Gram
//     dot4s, 2 shuffle pre-reduce rounds, STS from lanes 0-7 (9KB buffer)
//  B) 8 warps cooperatively reduce the 36 entries (LDS.64 + 5 shuffles)
//  C) warp 0: triangular recursion Gram -> T (GS transform, inverse norms
//     folded into the diagonal), broadcast via smem
//  D) apply b_i = sum_{k<=i} T[i][k] v_k, __stcs streaming store.
#define NV 8
#define DLEN 1024
#define NPROB 4096
#define NSTRIDE_F4 (NPROB * DLEN / 4)   // 1048576 float4 between n-slices
#define NG 36                           // lower-triangular entries

__device__ __forceinline__ float dot4(float4 a, float4 b) {
    return a.x * b.x + a.y * b.y + a.z * b.z + a.w * b.w;
}

__global__ void __launch_bounds__(256, 4)
gram_schmidt_kernel(const float* __restrict__ x, float* __restrict__ out) {
    const int p    = blockIdx.x;
    const int tid  = threadIdx.x;
    const int lane = tid & 31;
    const int warp = tid >> 5;

    const float4* __restrict__ xin =
        reinterpret_cast<const float4*>(x) + (size_t)p * (DLEN / 4) + tid;
    float4* __restrict__ xout =
        reinterpret_cast<float4*>(out) + (size_t)p * (DLEN / 4) + tid;

    __shared__ float part[NG][64];   // 9KB: 2-round pre-reduced Gram partials
    __shared__ float Gf[NG];         // reduced Gram (packed lower tri)
    __shared__ float Tm[NG];         // GS transform matrix (packed lower tri)

    // ---- A: load all 8 vectors (batched LDG.128.CG, L1 bypass) ----
    float4 v[NV];
    #pragma unroll
    for (int n = 0; n < NV; n++) v[n] = __ldcg(&xin[(size_t)n * NSTRIDE_F4]);

    // partial Gram, pre-reduced 2 shuffle rounds (lanes 0-7 store)
    #pragma unroll
    for (int i = 0; i < NV; i++) {
        #pragma unroll
        for (int j = 0; j <= i; j++) {
            float s = dot4(v[i], v[j]);
            s += __shfl_xor_sync(0xffffffffu, s, 16);
            s += __shfl_xor_sync(0xffffffffu, s, 8);
            if (lane < 8) part[i * (i + 1) / 2 + j][warp * 8 + lane] = s;
        }
    }
    __syncthreads();

    // ---- B: cooperative reduction, warp w handles entries w, w+8, ... ----
    for (int t = warp; t < NG; t += 8) {
        const float2* row = reinterpret_cast<const float2*>(part[t]);
        float2 a = row[lane];             // 32 lanes x float2 = 64 floats
        float s = a.x + a.y;
        s += __shfl_xor_sync(0xffffffffu, s, 16);
        s += __shfl_xor_sync(0xffffffffu, s, 8);
        s += __shfl_xor_sync(0xffffffffu, s, 4);
        s += __shfl_xor_sync(0xffffffffu, s, 2);
        s += __shfl_xor_sync(0xffffffffu, s, 1);
        if (lane == 0) Gf[t] = s;
    }
    __syncthreads();

    // ---- C: warp 0 computes the triangular recursion (replicated lanes) ----
    if (warp == 0) {
        float G[NG];
        #pragma unroll
        for (int t = 0; t < NG; t++) G[t] = Gf[t];  // broadcast LDS

        float T[NG];
        {
            float inv = (G[0] > 0.0f) ? rsqrtf(G[0]) : 0.0f;
            T[0] = inv;
        }
        #pragma unroll
        for (int i = 1; i < NV; i++) {
            float c[NV];
            #pragma unroll
            for (int j = 0; j < i; j++) {
                float s = 0.0f;
                #pragma unroll
                for (int k = 0; k <= j; k++)
                    s += T[j * (j + 1) / 2 + k] * G[i * (i + 1) / 2 + k];
                c[j] = s;
            }
            float n2 = G[i * (i + 1) / 2 + i];
            #pragma unroll
            for (int j = 0; j < i; j++) n2 -= c[j] * c[j];
            float inv = (n2 > 0.0f) ? rsqrtf(n2) : 0.0f;

            #pragma unroll
            for (int k = 0; k < i; k++) {
                float s = 0.0f;
                #pragma unroll
                for (int j = k; j < i; j++)
                    s -= c[j] * T[j * (j + 1) / 2 + k];
                T[i * (i + 1) / 2 + k] = s * inv;
            }
            T[i * (i + 1) / 2 + i] = inv;
        }
        if (lane == 0) {
            #pragma unroll
            for (int t = 0; t < NG; t++) Tm[t] = T[t];
        }
    }
    __syncthreads();

    // ---- D: apply b_i = sum_{k<=i} T[i][k] v_k, streaming store ----
    #pragma unroll
    for (int i = 0; i < NV; i++) {
        float4 acc = make_float4(0.0f, 0.0f, 0.0f, 0.0f);
        #pragma unroll
        for (int k = 0; k <= i; k++) {
            float t = Tm[i * (i + 1) / 2 + k];  // LDS broadcast
            acc.x += t * v[k].x;
            acc.y += t * v[k].y;
            acc.z += t * v[k].z;
            acc.w += t * v[k].w;
        }
        __stcs(&xout[(size_t)i * NSTRIDE_F4], acc);
    }
}

extern "C" void kernel_launch(void* const* d_in, const int* in_sizes, int n_in,
                              void* d_out, int out_size) {
    const float* x = (const float*)d_in[0];
    float* out = (float*)d_out;
    gram_schmidt_kernel<<<NPROB, 256>>>(x, out);
}

// round 12
// speedup vs baseline: 1.5606x; 1.0440x over previous
#include <cuda_runtime.h>

// x: (N=8, M=32, C=128, H=32, W=32) fp32.  D = H*W = 1024.
// 4096 independent classical Gram-Schmidt problems (one per (m,c)),
// each over NV=8 vectors of length 1024.
//
// R3-exact structure (empirically the best of this family):
// one block (256 threads) per problem, 1 float4/thread/vector.
//  A) load 8 float4 in two groups of 4, Gram dot4s interleaved with the
//     second load group, STS full-width partials to part[t][tid] (36KB)
//  B) 8 warps cooperatively reduce the 36 entries (2x LDS.128 + 5 shuffles)
//  C) warp 0: triangular recursion Gram -> T (GS transform, inverse norms
//     folded into the diagonal), broadcast via smem
//  D) apply b_i = sum_{k<=i} T[i][k] v_k, __stcs streaming store.
#define NV 8
#define DLEN 1024
#define NPROB 4096
#define NSTRIDE_F4 (NPROB * DLEN / 4)   // 1048576 float4 between n-slices
#define NG 36                           // lower-triangular entries

__device__ __forceinline__ float dot4(float4 a, float4 b) {
    return a.x * b.x + a.y * b.y + a.z * b.z + a.w * b.w;
}

__global__ void __launch_bounds__(256, 4)
gram_schmidt_kernel(const float* __restrict__ x, float* __restrict__ out) {
    const int p    = blockIdx.x;
    const int tid  = threadIdx.x;
    const int lane = tid & 31;
    const int warp = tid >> 5;

    const float4* __restrict__ xin =
        reinterpret_cast<const float4*>(x) + (size_t)p * (DLEN / 4) + tid;
    float4* __restrict__ xout =
        reinterpret_cast<float4*>(out) + (size_t)p * (DLEN / 4) + tid;

    __shared__ float part[NG][256];  // 36KB: per-thread Gram partials
    __shared__ float Gf[NG];         // reduced Gram (packed lower tri)
    __shared__ float Tm[NG];         // GS transform matrix (packed lower tri)

    // ---- A: load group 1 (v0..v3) ----
    float4 v[NV];
    #pragma unroll
    for (int n = 0; n < 4; n++) v[n] = xin[(size_t)n * NSTRIDE_F4];

    // issue group 2 loads (v4..v7); Gram on group 1 can overlap their flight
    #pragma unroll
    for (int n = 4; n < NV; n++) v[n] = xin[(size_t)n * NSTRIDE_F4];

    // Gram entries among v0..v3 first (only depend on group 1)
    #pragma unroll
    for (int i = 0; i < 4; i++) {
        #pragma unroll
        for (int j = 0; j <= i; j++) {
            part[i * (i + 1) / 2 + j][tid] = dot4(v[i], v[j]);
        }
    }
    // remaining Gram entries (depend on group 2)
    #pragma unroll
    for (int i = 4; i < NV; i++) {
        #pragma unroll
        for (int j = 0; j <= i; j++) {
            part[i * (i + 1) / 2 + j][tid] = dot4(v[i], v[j]);
        }
    }
    __syncthreads();

    // ---- B: cooperative reduction, warp w handles entries w, w+8, ... ----
    for (int t = warp; t < NG; t += 8) {
        const float4* row = reinterpret_cast<const float4*>(part[t]);
        float4 a = row[lane];
        float4 b = row[lane + 32];
        float s = (a.x + a.y) + (a.z + a.w) + (b.x + b.y) + (b.z + b.w);
        s += __shfl_xor_sync(0xffffffffu, s, 16);
        s += __shfl_xor_sync(0xffffffffu, s, 8);
        s += __shfl_xor_sync(0xffffffffu, s, 4);
        s += __shfl_xor_sync(0xffffffffu, s, 2);
        s += __shfl_xor_sync(0xffffffffu, s, 1);
        if (lane == 0) Gf[t] = s;
    }
    __syncthreads();

    // ---- C: warp 0 computes the triangular recursion (replicated lanes) ----
    if (warp == 0) {
        float G[NG];
        #pragma unroll
        for (int t = 0; t < NG; t++) G[t] = Gf[t];  // broadcast LDS

        float T[NG];
        {
            float inv = (G[0] > 0.0f) ? rsqrtf(G[0]) : 0.0f;
            T[0] = inv;
        }
        #pragma unroll
        for (int i = 1; i < NV; i++) {
            float c[NV];
            #pragma unroll
            for (int j = 0; j < i; j++) {
                float s = 0.0f;
                #pragma unroll
                for (int k = 0; k <= j; k++)
                    s += T[j * (j + 1) / 2 + k] * G[i * (i + 1) / 2 + k];
                c[j] = s;
            }
            float n2 = G[i * (i + 1) / 2 + i];
            #pragma unroll
            for (int j = 0; j < i; j++) n2 -= c[j] * c[j];
            float inv = (n2 > 0.0f) ? rsqrtf(n2) : 0.0f;

            #pragma unroll
            for (int k = 0; k < i; k++) {
                float s = 0.0f;
                #pragma unroll
                for (int j = k; j < i; j++)
                    s -= c[j] * T[j * (j + 1) / 2 + k];
                T[i * (i + 1) / 2 + k] = s * inv;
            }
            T[i * (i + 1) / 2 + i] = inv;
        }
        if (lane == 0) {
            #pragma unroll
            for (int t = 0; t < NG; t++) Tm[t] = T[t];
        }
    }
    __syncthreads();

    // ---- D: apply b_i = sum_{k<=i} T[i][k] v_k, streaming store ----
    #pragma unroll
    for (int i = 0; i < NV; i++) {
        float4 acc = make_float4(0.0f, 0.0f, 0.0f, 0.0f);
        #pragma unroll
        for (int k = 0; k <= i; k++) {
            float t = Tm[i * (i + 1) / 2 + k];  // LDS broadcast
            acc.x += t * v[k].x;
            acc.y += t * v[k].y;
            acc.z += t * v[k].z;
            acc.w += t * v[k].w;
        }
        __stcs(&xout[(size_t)i * NSTRIDE_F4], acc);
    }
}

extern "C" void kernel_launch(void* const* d_in, const int* in_sizes, int n_in,
                              void* d_out, int out_size) {
    const float* x = (const float*)d_in[0];
    float* out = (float*)d_out;
    gram_schmidt_kernel<<<NPROB, 256>>>(x, out);
}